// round 15
// baseline (speedup 1.0000x reference)
#include <cuda_runtime.h>
#include <cuda_bf16.h>
#include <cuda_fp16.h>
#include <cstdint>
#include <cstddef>

// Problem dims
#define BSZ  32
#define SEQ  2048
#define IND  512
#define HID  256
#define MROWS (BSZ * SEQ)          // 65536
#define NLANE (BSZ * HID)          // 8192 per direction

// ---------------- scratch (device globals; no allocs allowed) ---------------
// packed element = (bf16_hi << 16) | bf16_lo ; value = hi + lo (~fp32 precise)
__device__ uint32_t g_Pp[MROWS * HID];          // fc output, packed
__device__ uint32_t g_Yp[2 * MROWS * HID];      // layer0 outputs, packed [ltr|rtl]
__device__ __half   g_S0[MROWS * HID];          // layer0 gate: (sigma-0.5) fp16
__device__ __half   g_S1[2 * MROWS * HID];      // layer1 gate
__device__ uint32_t g_W2p[2 * HID * HID];       // W2 packed (both layers)

__device__ __forceinline__ float tanh_fast(float x) {
    float y;
    asm("tanh.approx.f32 %0, %1;" : "=f"(y) : "f"(x));
    return y;
}

__device__ __forceinline__ uint32_t smem_u32(const void* p) {
    uint32_t a;
    asm("{ .reg .u64 t; cvta.to.shared.u64 t, %1; cvt.u32.u64 %0, t; }"
        : "=r"(a) : "l"(p));
    return a;
}

__device__ __forceinline__ uint32_t prmt(uint32_t a, uint32_t b, uint32_t sel) {
    uint32_t r;
    asm("prmt.b32 %0, %1, %2, %3;" : "=r"(r) : "r"(a), "r"(b), "r"(sel));
    return r;
}

__device__ __forceinline__ void split2(float a, float b, uint32_t& hi, uint32_t& lo) {
    __nv_bfloat16 ha = __float2bfloat16_rn(a);
    __nv_bfloat16 hb = __float2bfloat16_rn(b);
    float ra = a - __bfloat162float(ha);
    float rb = b - __bfloat162float(hb);
    __nv_bfloat162 hh; hh.x = ha; hh.y = hb;
    __nv_bfloat162 ll = __floats2bfloat162_rn(ra, rb);
    hi = *reinterpret_cast<uint32_t*>(&hh);
    lo = *reinterpret_cast<uint32_t*>(&ll);
}

__device__ __forceinline__ uint32_t pack_hl(float v) {
    __nv_bfloat16 hb = __float2bfloat16_rn(v);
    float r = v - __bfloat162float(hb);
    __nv_bfloat16 lb = __float2bfloat16_rn(r);
    return ((uint32_t)*reinterpret_cast<unsigned short*>(&hb) << 16)
         |  (uint32_t)*reinterpret_cast<unsigned short*>(&lb);
}

__device__ __forceinline__ float unpack_hl(uint32_t p) {
    float hi = __uint_as_float(p & 0xFFFF0000u);
    float lo = __uint_as_float(p << 16);
    return hi + lo;
}

__device__ __forceinline__ void mma16816(
    float c[4], uint32_t a0, uint32_t a1, uint32_t a2, uint32_t a3,
    uint32_t b0, uint32_t b1)
{
    asm volatile(
        "mma.sync.aligned.m16n8k16.row.col.f32.bf16.bf16.f32 "
        "{%0,%1,%2,%3}, {%4,%5,%6,%7}, {%8,%9}, {%0,%1,%2,%3};"
        : "+f"(c[0]), "+f"(c[1]), "+f"(c[2]), "+f"(c[3])
        : "r"(a0), "r"(a1), "r"(a2), "r"(a3), "r"(b0), "r"(b1));
}

#define LDSM_X4(r0, r1, r2, r3, addr) \
    asm volatile("ldmatrix.sync.aligned.m8n8.x4.shared.b16 {%0,%1,%2,%3}, [%4];" \
        : "=r"(r0), "=r"(r1), "=r"(r2), "=r"(r3) : "r"(addr))

#define SB 80   // smem row stride bytes (64B data + 16B pad)

// ===========================================================================
// GEMM compute core: BM=128, BN=128, BK=32; 8 warps (4Mx2N), warp tile 32x64.
// ===========================================================================
struct GemmCtx {
    uint32_t uAh, uAl, uWh, uWl;
    uint32_t aoff, boff;
    int wm, wn, r, q;
};

__device__ __forceinline__ void gemm_compute(
    const GemmCtx& g, float acc[2][8][4])
{
    #pragma unroll
    for (int pass = 0; pass < 3; pass++) {
        const uint32_t uAt = (pass == 1) ? g.uAl : g.uAh;
        const uint32_t uWt = (pass == 2) ? g.uWl : g.uWh;
        const uint32_t aBase = uAt + (uint32_t)(g.wm * SB) + g.aoff;
        const uint32_t bBase = uWt + (uint32_t)(g.wn * SB) + g.boff;
        #pragma unroll
        for (int ks = 0; ks < 2; ks++) {
            const uint32_t ko = ks * 32;
            uint32_t bfr[8][2];
            #pragma unroll
            for (int p = 0; p < 4; p++) {
                LDSM_X4(bfr[2*p][0], bfr[2*p][1], bfr[2*p+1][0], bfr[2*p+1][1],
                        bBase + (uint32_t)(p * 16 * SB) + ko);
            }
            #pragma unroll
            for (int mt = 0; mt < 2; mt++) {
                uint32_t a0, a1, a2, a3;
                LDSM_X4(a0, a1, a2, a3, aBase + (uint32_t)(mt * 16 * SB) + ko);
                #pragma unroll
                for (int nt = 0; nt < 8; nt++)
                    mma16816(acc[mt][nt], a0, a1, a2, a3, bfr[nt][0], bfr[nt][1]);
            }
        }
    }
}

// ---------------------------------------------------------------------------
// fc GEMM: fp32 inputs (x, W_fc), split in loader, epilogue packs to u32.
// ---------------------------------------------------------------------------
__global__ __launch_bounds__(256, 2) void gemm_fc(
    const float* __restrict__ A, const float* __restrict__ W,
    const float* __restrict__ bias, uint32_t* __restrict__ Cp)
{
    __shared__ __align__(16) char sAh[128 * SB];
    __shared__ __align__(16) char sAl[128 * SB];
    __shared__ __align__(16) char sWh[128 * SB];
    __shared__ __align__(16) char sWl[128 * SB];

    const int tid  = threadIdx.x;
    const int lane = tid & 31;
    const int warp = tid >> 5;
    GemmCtx g;
    g.wm = (warp & 3) * 32; g.wn = (warp >> 2) * 64;
    g.r = lane >> 2; g.q = lane & 3;
    g.uAh = smem_u32(sAh); g.uAl = smem_u32(sAl);
    g.uWh = smem_u32(sWh); g.uWl = smem_u32(sWl);
    g.aoff = (uint32_t)((lane & 15) * SB + ((lane >> 4) << 4));
    g.boff = (uint32_t)(((lane & 7) + (lane >> 4) * 8) * SB + ((lane & 8) << 1));

    const int bm  = blockIdx.x * 128;
    const int bnG = blockIdx.y * 128;
    const int K = IND;

    float acc[2][8][4];
    #pragma unroll
    for (int mt = 0; mt < 2; mt++)
        #pragma unroll
        for (int nt = 0; nt < 8; nt++)
            #pragma unroll
            for (int e = 0; e < 4; e++) acc[mt][nt][e] = 0.f;

    for (int c = 0; c < (K >> 5); c++) {
        const int k0 = c << 5;
        #pragma unroll
        for (int i = 0; i < 4; i++) {
            int idx = i * 256 + tid;
            int row = idx >> 3;
            int c4  = (idx & 7) * 4;
            float4 va = *reinterpret_cast<const float4*>(
                &A[(size_t)(bm + row) * K + k0 + c4]);
            float4 vw = *reinterpret_cast<const float4*>(
                &W[(size_t)(bnG + row) * K + k0 + c4]);
            uint2 ahi, alo, whi, wlo;
            split2(va.x, va.y, ahi.x, alo.x);
            split2(va.z, va.w, ahi.y, alo.y);
            split2(vw.x, vw.y, whi.x, wlo.x);
            split2(vw.z, vw.w, whi.y, wlo.y);
            int off = row * SB + c4 * 2;
            *reinterpret_cast<uint2*>(sAh + off) = ahi;
            *reinterpret_cast<uint2*>(sAl + off) = alo;
            *reinterpret_cast<uint2*>(sWh + off) = whi;
            *reinterpret_cast<uint2*>(sWl + off) = wlo;
        }
        __syncthreads();
        gemm_compute(g, acc);
        __syncthreads();
    }

    #pragma unroll
    for (int mt = 0; mt < 2; mt++) {
        const int row = bm + g.wm + mt * 16 + g.r;
        #pragma unroll
        for (int nt = 0; nt < 8; nt++) {
            const int col = bnG + g.wn + nt * 8 + g.q * 2;
            float b0 = bias[col], b1 = bias[col + 1];
            uint2 p0, p1;
            p0.x = pack_hl(acc[mt][nt][0] + b0);
            p0.y = pack_hl(acc[mt][nt][1] + b1);
            p1.x = pack_hl(acc[mt][nt][2] + b0);
            p1.y = pack_hl(acc[mt][nt][3] + b1);
            *reinterpret_cast<uint2*>(&Cp[(size_t)row * 256 + col]) = p0;
            *reinterpret_cast<uint2*>(&Cp[(size_t)(row + 8) * 256 + col]) = p1;
        }
    }
}

// ---------------------------------------------------------------------------
// Gate GEMM: packed u32 inputs, PRMT loader, K=256, single-buffered.
// Epilogue writes ONLY (sigma-0.5) = 0.5*tanh(z/2) as fp16.
// ---------------------------------------------------------------------------
__global__ __launch_bounds__(256, 2) void gemm_gate(
    const uint32_t* __restrict__ Ap, const uint32_t* __restrict__ Wp,
    const float* __restrict__ bias, __half* __restrict__ S)
{
    __shared__ __align__(16) char sAh[128 * SB];
    __shared__ __align__(16) char sAl[128 * SB];
    __shared__ __align__(16) char sWh[128 * SB];
    __shared__ __align__(16) char sWl[128 * SB];

    const int tid  = threadIdx.x;
    const int lane = tid & 31;
    const int warp = tid >> 5;
    GemmCtx g;
    g.wm = (warp & 3) * 32; g.wn = (warp >> 2) * 64;
    g.r = lane >> 2; g.q = lane & 3;
    g.uAh = smem_u32(sAh); g.uAl = smem_u32(sAl);
    g.uWh = smem_u32(sWh); g.uWl = smem_u32(sWl);
    g.aoff = (uint32_t)((lane & 15) * SB + ((lane >> 4) << 4));
    g.boff = (uint32_t)(((lane & 7) + (lane >> 4) * 8) * SB + ((lane & 8) << 1));

    const int bm  = blockIdx.x * 128;
    const int bnG = blockIdx.y * 128;
    const int K = HID;   // 256

    float acc[2][8][4];
    #pragma unroll
    for (int mt = 0; mt < 2; mt++)
        #pragma unroll
        for (int nt = 0; nt < 8; nt++)
            #pragma unroll
            for (int e = 0; e < 4; e++) acc[mt][nt][e] = 0.f;

    for (int c = 0; c < (K >> 5); c++) {
        const int k0 = c << 5;
        #pragma unroll
        for (int i = 0; i < 4; i++) {
            int idx = i * 256 + tid;
            int row = idx >> 3;
            int c4  = (idx & 7) * 4;
            uint4 va = *reinterpret_cast<const uint4*>(
                &Ap[(size_t)(bm + row) * K + k0 + c4]);
            uint4 vw = *reinterpret_cast<const uint4*>(
                &Wp[(size_t)(bnG + row) * K + k0 + c4]);
            uint2 ahi, alo, whi, wlo;
            ahi.x = prmt(va.x, va.y, 0x7632); alo.x = prmt(va.x, va.y, 0x5410);
            ahi.y = prmt(va.z, va.w, 0x7632); alo.y = prmt(va.z, va.w, 0x5410);
            whi.x = prmt(vw.x, vw.y, 0x7632); wlo.x = prmt(vw.x, vw.y, 0x5410);
            whi.y = prmt(vw.z, vw.w, 0x7632); wlo.y = prmt(vw.z, vw.w, 0x5410);
            int off = row * SB + c4 * 2;
            *reinterpret_cast<uint2*>(sAh + off) = ahi;
            *reinterpret_cast<uint2*>(sAl + off) = alo;
            *reinterpret_cast<uint2*>(sWh + off) = whi;
            *reinterpret_cast<uint2*>(sWl + off) = wlo;
        }
        __syncthreads();
        gemm_compute(g, acc);
        __syncthreads();
    }

    // epilogue: s = 0.5*tanh(z/2) = sigma(z) - 0.5, fp16 store only
    #pragma unroll
    for (int mt = 0; mt < 2; mt++) {
        const int row = bm + g.wm + mt * 16 + g.r;
        #pragma unroll
        for (int nt = 0; nt < 8; nt++) {
            const int col = bnG + g.wn + nt * 8 + g.q * 2;
            float b0 = bias[col], b1 = bias[col + 1];
            float s00 = 0.5f * tanh_fast(0.5f * (acc[mt][nt][0] + b0));
            float s01 = 0.5f * tanh_fast(0.5f * (acc[mt][nt][1] + b1));
            float s10 = 0.5f * tanh_fast(0.5f * (acc[mt][nt][2] + b0));
            float s11 = 0.5f * tanh_fast(0.5f * (acc[mt][nt][3] + b1));
            *reinterpret_cast<__half2*>(&S[(size_t)row * 256 + col])
                = __floats2half2_rn(s00, s01);
            *reinterpret_cast<__half2*>(&S[(size_t)(row + 8) * 256 + col])
                = __floats2half2_rn(s10, s11);
        }
    }
}

// ---------------------------------------------------------------------------
__global__ __launch_bounds__(256) void prep_w(const float* __restrict__ W2,
                                              uint32_t* __restrict__ W2p)
{
    int i = blockIdx.x * blockDim.x + threadIdx.x;
    W2p[i] = pack_hl(W2[i]);
}

// ---------------------------------------------------------------------------
// Recurrence: x packed u32 + gate (sigma-0.5) fp16, two streams; ring depth 32.
// POUT: write packed u32 (layer0) else fp32 (layer1 -> d_out).
// ---------------------------------------------------------------------------
#define PD 32

template <bool POUT>
__global__ __launch_bounds__(128) void recur2(
    const uint32_t* __restrict__ X0, const __half* __restrict__ S0,
    uint32_t* __restrict__ P0, float* __restrict__ F0, int yld0, int yoff0,
    const uint32_t* __restrict__ X1, const __half* __restrict__ S1,
    uint32_t* __restrict__ P1, float* __restrict__ F1, int yld1, int yoff1)
{
    const int dir = blockIdx.y;
    const uint32_t* __restrict__ X = dir ? X1 : X0;
    const __half* __restrict__ Sg  = dir ? S1 : S0;
    uint32_t* __restrict__ Yp = dir ? P1 : P0;
    float*    __restrict__ Yf = dir ? F1 : F0;
    const int yld  = dir ? yld1  : yld0;
    const int yoff = dir ? yoff1 : yoff0;

    const int gg = blockIdx.x * blockDim.x + threadIdx.x;
    const int b = gg >> 8;
    const int j = gg & 255;

    const int t0 = dir ? (SEQ - 1) : 0;
    const ptrdiff_t xstep = dir ? -(ptrdiff_t)HID : (ptrdiff_t)HID;
    const ptrdiff_t ystep = dir ? -(ptrdiff_t)yld : (ptrdiff_t)yld;

    const uint32_t* xp = X + ((size_t)b * SEQ + t0) * HID + j;
    const __half*   sp = Sg + ((size_t)b * SEQ + t0) * HID + j;
    const size_t ybase = (size_t)b * SEQ * yld + (size_t)t0 * yld + yoff + j;
    uint32_t* ypp = POUT ? (Yp + ybase) : nullptr;
    float*    ypf = POUT ? nullptr : (Yf + ybase);

    uint32_t xr[PD];
    __half   sr[PD];
    #pragma unroll
    for (int d = 0; d < PD; d++) {
        xr[d] = xp[(ptrdiff_t)d * xstep];
        sr[d] = sp[(ptrdiff_t)d * xstep];
    }
    const uint32_t* xq = xp + (ptrdiff_t)PD * xstep;
    const __half*   sq = sp + (ptrdiff_t)PD * xstep;

    float h = 0.f;
    #pragma unroll 1
    for (int blk = 0; blk < SEQ / PD - 1; blk++) {
        #pragma unroll
        for (int d = 0; d < PD; d++) {
            float xv = unpack_hl(xr[d]);
            float a  = 0.5f + __half2float(sr[d]);   // sigma
            float c  = fmaf(-a, xv, xv);
            float t  = fmaf(a, h, c);
            h = tanh_fast(xv * t);
            if (POUT) { *ypp = pack_hl(h); ypp += ystep; }
            else      { *ypf = h;          ypf += ystep; }
            xr[d] = *xq;
            sr[d] = *sq;
            xq += xstep;
            sq += xstep;
        }
    }
    #pragma unroll
    for (int d = 0; d < PD; d++) {
        float xv = unpack_hl(xr[d]);
        float a  = 0.5f + __half2float(sr[d]);
        float c  = fmaf(-a, xv, xv);
        float t  = fmaf(a, h, c);
        h = tanh_fast(xv * t);
        if (POUT) { *ypp = pack_hl(h); ypp += ystep; }
        else      { *ypf = h;          ypf += ystep; }
    }
}

// ---------------------------------------------------------------------------
__global__ __launch_bounds__(256) void copy_hout(
    const uint32_t* __restrict__ Ypl, const uint32_t* __restrict__ Ypr,
    const float* __restrict__ xx, float* __restrict__ hout)
{
    int gg = blockIdx.x * blockDim.x + threadIdx.x;
    int j = gg & 255;
    int b = (gg >> 8) & 31;
    int s = gg >> 13;
    float v;
    if      (s == 0) v = unpack_hl(Ypl[((size_t)b * SEQ + (SEQ - 1)) * HID + j]);
    else if (s == 1) v = unpack_hl(Ypr[((size_t)b * SEQ) * HID + j]);
    else if (s == 2) v = xx[((size_t)b * SEQ + (SEQ - 1)) * (2 * HID) + j];
    else             v = xx[((size_t)b * SEQ) * (2 * HID) + HID + j];
    hout[gg] = v;
}

// ---------------------------------------------------------------------------
extern "C" void kernel_launch(void* const* d_in, const int* in_sizes, int n_in,
                              void* d_out, int out_size)
{
    const float* x    = (const float*)d_in[0];
    const float* W_fc = (const float*)d_in[1];
    const float* b_fc = (const float*)d_in[2];
    // d_in[3] = W1, d_in[4] = b1 : dead (g1*x + (1-g1)*x == x)
    const float* W2   = (const float*)d_in[5];
    const float* b2   = (const float*)d_in[6];
    float* out = (float*)d_out;

    uint32_t *Pp, *Yp, *W2p;
    __half *S0, *S1;
    cudaGetSymbolAddress((void**)&Pp,  g_Pp);
    cudaGetSymbolAddress((void**)&Yp,  g_Yp);
    cudaGetSymbolAddress((void**)&S0,  g_S0);
    cudaGetSymbolAddress((void**)&S1,  g_S1);
    cudaGetSymbolAddress((void**)&W2p, g_W2p);

    uint32_t* Ypl = Yp;
    uint32_t* Ypr = Yp + (size_t)MROWS * HID;
    float* hout = out + (size_t)BSZ * SEQ * 2 * HID;

    // 0) pre-split W2 (both layers) into packed format
    prep_w<<<2 * HID * HID / 256, 256>>>(W2, W2p);

    // 1) fc projection -> packed P
    {
        dim3 grid(MROWS / 128, 2);
        gemm_fc<<<grid, 256>>>(x, W_fc, b_fc, Pp);
    }

    // 2) layer 0 gates (shared by both dirs) -> (sigma-0.5) fp16
    {
        dim3 grid(MROWS / 128, 2);
        gemm_gate<<<grid, 256>>>(Pp, W2p, b2, S0);
    }

    // 3) layer 0 recurrence -> packed Y
    {
        dim3 grid(NLANE / 128, 2);
        recur2<true><<<grid, 128>>>(Pp, S0, Ypl, nullptr, HID, 0,
                                    Pp, S0, Ypr, nullptr, HID, 0);
    }

    // 4) layer 1 gates: one GEMM over [2*MROWS, 256]
    {
        dim3 grid(2 * MROWS / 128, 2);
        gemm_gate<<<grid, 256>>>(Yp, W2p + HID * HID, b2 + HID, S1);
    }

    // 5) layer 1 recurrence -> d_out fp32 (feature stride 512)
    {
        dim3 grid(NLANE / 128, 2);
        recur2<false><<<grid, 128>>>(Ypl, S1, nullptr, out, 2 * HID, 0,
                                     Ypr, S1 + (size_t)MROWS * HID, nullptr, out, 2 * HID, HID);
    }

    // 6) final hidden states
    copy_hout<<<BSZ * HID * 4 / 256, 256>>>(Ypl, Ypr, out, hout);
}

// round 17
// speedup vs baseline: 1.2151x; 1.2151x over previous
#include <cuda_runtime.h>
#include <cuda_bf16.h>
#include <cuda_fp16.h>
#include <cstdint>
#include <cstddef>

// Problem dims
#define BSZ  32
#define SEQ  2048
#define IND  512
#define HID  256
#define MROWS (BSZ * SEQ)          // 65536
#define NLANE (BSZ * HID)          // 8192 per direction

// ---------------- scratch (device globals; no allocs allowed) ---------------
// packed element = (bf16_hi << 16) | bf16_lo ; value = hi + lo (~fp32 precise)
__device__ uint32_t g_Pp[MROWS * HID];          // fc output, packed
__device__ uint32_t g_Yp[2 * MROWS * HID];      // layer0 outputs, packed [ltr|rtl]
__device__ __half   g_S0[MROWS * HID];          // layer0 gate: (sigma-0.5) fp16
__device__ __half   g_S1[2 * MROWS * HID];      // layer1 gate
__device__ uint32_t g_W2p[2 * HID * HID];       // W2 packed (both layers)

__device__ __forceinline__ float tanh_fast(float x) {
    float y;
    asm("tanh.approx.f32 %0, %1;" : "=f"(y) : "f"(x));
    return y;
}

__device__ __forceinline__ uint32_t smem_u32(const void* p) {
    uint32_t a;
    asm("{ .reg .u64 t; cvta.to.shared.u64 t, %1; cvt.u32.u64 %0, t; }"
        : "=r"(a) : "l"(p));
    return a;
}

__device__ __forceinline__ uint32_t prmt(uint32_t a, uint32_t b, uint32_t sel) {
    uint32_t r;
    asm("prmt.b32 %0, %1, %2, %3;" : "=r"(r) : "r"(a), "r"(b), "r"(sel));
    return r;
}

__device__ __forceinline__ void split2(float a, float b, uint32_t& hi, uint32_t& lo) {
    __nv_bfloat16 ha = __float2bfloat16_rn(a);
    __nv_bfloat16 hb = __float2bfloat16_rn(b);
    float ra = a - __bfloat162float(ha);
    float rb = b - __bfloat162float(hb);
    __nv_bfloat162 hh; hh.x = ha; hh.y = hb;
    __nv_bfloat162 ll = __floats2bfloat162_rn(ra, rb);
    hi = *reinterpret_cast<uint32_t*>(&hh);
    lo = *reinterpret_cast<uint32_t*>(&ll);
}

__device__ __forceinline__ uint32_t pack_hl(float v) {
    __nv_bfloat16 hb = __float2bfloat16_rn(v);
    float r = v - __bfloat162float(hb);
    __nv_bfloat16 lb = __float2bfloat16_rn(r);
    return ((uint32_t)*reinterpret_cast<unsigned short*>(&hb) << 16)
         |  (uint32_t)*reinterpret_cast<unsigned short*>(&lb);
}

__device__ __forceinline__ float unpack_hl(uint32_t p) {
    float hi = __uint_as_float(p & 0xFFFF0000u);
    float lo = __uint_as_float(p << 16);
    return hi + lo;
}

__device__ __forceinline__ void mma16816(
    float c[4], uint32_t a0, uint32_t a1, uint32_t a2, uint32_t a3,
    uint32_t b0, uint32_t b1)
{
    asm volatile(
        "mma.sync.aligned.m16n8k16.row.col.f32.bf16.bf16.f32 "
        "{%0,%1,%2,%3}, {%4,%5,%6,%7}, {%8,%9}, {%0,%1,%2,%3};"
        : "+f"(c[0]), "+f"(c[1]), "+f"(c[2]), "+f"(c[3])
        : "r"(a0), "r"(a1), "r"(a2), "r"(a3), "r"(b0), "r"(b1));
}

#define LDSM_X4(r0, r1, r2, r3, addr) \
    asm volatile("ldmatrix.sync.aligned.m8n8.x4.shared.b16 {%0,%1,%2,%3}, [%4];" \
        : "=r"(r0), "=r"(r1), "=r"(r2), "=r"(r3) : "r"(addr))

#define SB 80   // smem row stride bytes (64B data + 16B pad)

// ===========================================================================
// GEMM compute core: BM=128, BN=128, BK=32; 8 warps (4Mx2N), warp tile 32x64.
// ===========================================================================
struct GemmCtx {
    uint32_t uAh, uAl, uWh, uWl;
    uint32_t aoff, boff;
    int wm, wn, r, q;
};

__device__ __forceinline__ void gemm_compute(
    const GemmCtx& g, float acc[2][8][4])
{
    #pragma unroll
    for (int pass = 0; pass < 3; pass++) {
        const uint32_t uAt = (pass == 1) ? g.uAl : g.uAh;
        const uint32_t uWt = (pass == 2) ? g.uWl : g.uWh;
        const uint32_t aBase = uAt + (uint32_t)(g.wm * SB) + g.aoff;
        const uint32_t bBase = uWt + (uint32_t)(g.wn * SB) + g.boff;
        #pragma unroll
        for (int ks = 0; ks < 2; ks++) {
            const uint32_t ko = ks * 32;
            uint32_t bfr[8][2];
            #pragma unroll
            for (int p = 0; p < 4; p++) {
                LDSM_X4(bfr[2*p][0], bfr[2*p][1], bfr[2*p+1][0], bfr[2*p+1][1],
                        bBase + (uint32_t)(p * 16 * SB) + ko);
            }
            #pragma unroll
            for (int mt = 0; mt < 2; mt++) {
                uint32_t a0, a1, a2, a3;
                LDSM_X4(a0, a1, a2, a3, aBase + (uint32_t)(mt * 16 * SB) + ko);
                #pragma unroll
                for (int nt = 0; nt < 8; nt++)
                    mma16816(acc[mt][nt], a0, a1, a2, a3, bfr[nt][0], bfr[nt][1]);
            }
        }
    }
}

// ---------------------------------------------------------------------------
// fc GEMM: fp32 inputs (x, W_fc), split in loader, epilogue packs to u32.
// ---------------------------------------------------------------------------
__global__ __launch_bounds__(256, 2) void gemm_fc(
    const float* __restrict__ A, const float* __restrict__ W,
    const float* __restrict__ bias, uint32_t* __restrict__ Cp)
{
    __shared__ __align__(16) char sAh[128 * SB];
    __shared__ __align__(16) char sAl[128 * SB];
    __shared__ __align__(16) char sWh[128 * SB];
    __shared__ __align__(16) char sWl[128 * SB];

    const int tid  = threadIdx.x;
    const int lane = tid & 31;
    const int warp = tid >> 5;
    GemmCtx g;
    g.wm = (warp & 3) * 32; g.wn = (warp >> 2) * 64;
    g.r = lane >> 2; g.q = lane & 3;
    g.uAh = smem_u32(sAh); g.uAl = smem_u32(sAl);
    g.uWh = smem_u32(sWh); g.uWl = smem_u32(sWl);
    g.aoff = (uint32_t)((lane & 15) * SB + ((lane >> 4) << 4));
    g.boff = (uint32_t)(((lane & 7) + (lane >> 4) * 8) * SB + ((lane & 8) << 1));

    const int bm  = blockIdx.x * 128;
    const int bnG = blockIdx.y * 128;
    const int K = IND;

    float acc[2][8][4];
    #pragma unroll
    for (int mt = 0; mt < 2; mt++)
        #pragma unroll
        for (int nt = 0; nt < 8; nt++)
            #pragma unroll
            for (int e = 0; e < 4; e++) acc[mt][nt][e] = 0.f;

    for (int c = 0; c < (K >> 5); c++) {
        const int k0 = c << 5;
        #pragma unroll
        for (int i = 0; i < 4; i++) {
            int idx = i * 256 + tid;
            int row = idx >> 3;
            int c4  = (idx & 7) * 4;
            float4 va = *reinterpret_cast<const float4*>(
                &A[(size_t)(bm + row) * K + k0 + c4]);
            float4 vw = *reinterpret_cast<const float4*>(
                &W[(size_t)(bnG + row) * K + k0 + c4]);
            uint2 ahi, alo, whi, wlo;
            split2(va.x, va.y, ahi.x, alo.x);
            split2(va.z, va.w, ahi.y, alo.y);
            split2(vw.x, vw.y, whi.x, wlo.x);
            split2(vw.z, vw.w, whi.y, wlo.y);
            int off = row * SB + c4 * 2;
            *reinterpret_cast<uint2*>(sAh + off) = ahi;
            *reinterpret_cast<uint2*>(sAl + off) = alo;
            *reinterpret_cast<uint2*>(sWh + off) = whi;
            *reinterpret_cast<uint2*>(sWl + off) = wlo;
        }
        __syncthreads();
        gemm_compute(g, acc);
        __syncthreads();
    }

    #pragma unroll
    for (int mt = 0; mt < 2; mt++) {
        const int row = bm + g.wm + mt * 16 + g.r;
        #pragma unroll
        for (int nt = 0; nt < 8; nt++) {
            const int col = bnG + g.wn + nt * 8 + g.q * 2;
            float b0 = bias[col], b1 = bias[col + 1];
            uint2 p0, p1;
            p0.x = pack_hl(acc[mt][nt][0] + b0);
            p0.y = pack_hl(acc[mt][nt][1] + b1);
            p1.x = pack_hl(acc[mt][nt][2] + b0);
            p1.y = pack_hl(acc[mt][nt][3] + b1);
            *reinterpret_cast<uint2*>(&Cp[(size_t)row * 256 + col]) = p0;
            *reinterpret_cast<uint2*>(&Cp[(size_t)(row + 8) * 256 + col]) = p1;
        }
    }
}

// ---------------------------------------------------------------------------
// Gate GEMM: packed u32 inputs, PRMT loader, K=256, single-buffered.
// Epilogue writes ONLY (sigma-0.5) = 0.5*tanh(z/2) as fp16.
// ---------------------------------------------------------------------------
__global__ __launch_bounds__(256, 2) void gemm_gate(
    const uint32_t* __restrict__ Ap, const uint32_t* __restrict__ Wp,
    const float* __restrict__ bias, __half* __restrict__ S)
{
    __shared__ __align__(16) char sAh[128 * SB];
    __shared__ __align__(16) char sAl[128 * SB];
    __shared__ __align__(16) char sWh[128 * SB];
    __shared__ __align__(16) char sWl[128 * SB];

    const int tid  = threadIdx.x;
    const int lane = tid & 31;
    const int warp = tid >> 5;
    GemmCtx g;
    g.wm = (warp & 3) * 32; g.wn = (warp >> 2) * 64;
    g.r = lane >> 2; g.q = lane & 3;
    g.uAh = smem_u32(sAh); g.uAl = smem_u32(sAl);
    g.uWh = smem_u32(sWh); g.uWl = smem_u32(sWl);
    g.aoff = (uint32_t)((lane & 15) * SB + ((lane >> 4) << 4));
    g.boff = (uint32_t)(((lane & 7) + (lane >> 4) * 8) * SB + ((lane & 8) << 1));

    const int bm  = blockIdx.x * 128;
    const int bnG = blockIdx.y * 128;
    const int K = HID;   // 256

    float acc[2][8][4];
    #pragma unroll
    for (int mt = 0; mt < 2; mt++)
        #pragma unroll
        for (int nt = 0; nt < 8; nt++)
            #pragma unroll
            for (int e = 0; e < 4; e++) acc[mt][nt][e] = 0.f;

    for (int c = 0; c < (K >> 5); c++) {
        const int k0 = c << 5;
        #pragma unroll
        for (int i = 0; i < 4; i++) {
            int idx = i * 256 + tid;
            int row = idx >> 3;
            int c4  = (idx & 7) * 4;
            uint4 va = *reinterpret_cast<const uint4*>(
                &Ap[(size_t)(bm + row) * K + k0 + c4]);
            uint4 vw = *reinterpret_cast<const uint4*>(
                &Wp[(size_t)(bnG + row) * K + k0 + c4]);
            uint2 ahi, alo, whi, wlo;
            ahi.x = prmt(va.x, va.y, 0x7632); alo.x = prmt(va.x, va.y, 0x5410);
            ahi.y = prmt(va.z, va.w, 0x7632); alo.y = prmt(va.z, va.w, 0x5410);
            whi.x = prmt(vw.x, vw.y, 0x7632); wlo.x = prmt(vw.x, vw.y, 0x5410);
            whi.y = prmt(vw.z, vw.w, 0x7632); wlo.y = prmt(vw.z, vw.w, 0x5410);
            int off = row * SB + c4 * 2;
            *reinterpret_cast<uint2*>(sAh + off) = ahi;
            *reinterpret_cast<uint2*>(sAl + off) = alo;
            *reinterpret_cast<uint2*>(sWh + off) = whi;
            *reinterpret_cast<uint2*>(sWl + off) = wlo;
        }
        __syncthreads();
        gemm_compute(g, acc);
        __syncthreads();
    }

    // epilogue: s = 0.5*tanh(z/2) = sigma(z) - 0.5, fp16 store only
    #pragma unroll
    for (int mt = 0; mt < 2; mt++) {
        const int row = bm + g.wm + mt * 16 + g.r;
        #pragma unroll
        for (int nt = 0; nt < 8; nt++) {
            const int col = bnG + g.wn + nt * 8 + g.q * 2;
            float b0 = bias[col], b1 = bias[col + 1];
            float s00 = 0.5f * tanh_fast(0.5f * (acc[mt][nt][0] + b0));
            float s01 = 0.5f * tanh_fast(0.5f * (acc[mt][nt][1] + b1));
            float s10 = 0.5f * tanh_fast(0.5f * (acc[mt][nt][2] + b0));
            float s11 = 0.5f * tanh_fast(0.5f * (acc[mt][nt][3] + b1));
            *reinterpret_cast<__half2*>(&S[(size_t)row * 256 + col])
                = __floats2half2_rn(s00, s01);
            *reinterpret_cast<__half2*>(&S[(size_t)(row + 8) * 256 + col])
                = __floats2half2_rn(s10, s11);
        }
    }
}

// ---------------------------------------------------------------------------
__global__ __launch_bounds__(256) void prep_w(const float* __restrict__ W2,
                                              uint32_t* __restrict__ W2p)
{
    int i = blockIdx.x * blockDim.x + threadIdx.x;
    W2p[i] = pack_hl(W2[i]);
}

// ---------------------------------------------------------------------------
// Recurrence: each thread owns TWO adjacent lanes (j, j+1).
// Loads: uint2 (x pair) + u32/half2 (gate pair). Ring depth 16 (16 | 2048).
// POUT: write packed uint2 (layer0) else float2 (layer1 -> d_out).
// ---------------------------------------------------------------------------
#define PD 16

template <bool POUT>
__global__ __launch_bounds__(64) void recur2(
    const uint32_t* __restrict__ X0, const __half* __restrict__ S0,
    uint32_t* __restrict__ P0, float* __restrict__ F0, int yld0, int yoff0,
    const uint32_t* __restrict__ X1, const __half* __restrict__ S1,
    uint32_t* __restrict__ P1, float* __restrict__ F1, int yld1, int yoff1)
{
    const int dir = blockIdx.y;
    const uint32_t* __restrict__ X = dir ? X1 : X0;
    const __half* __restrict__ Sg  = dir ? S1 : S0;
    uint32_t* __restrict__ Yp = dir ? P1 : P0;
    float*    __restrict__ Yf = dir ? F1 : F0;
    const int yld  = dir ? yld1  : yld0;
    const int yoff = dir ? yoff1 : yoff0;

    const int gg = blockIdx.x * blockDim.x + threadIdx.x;  // 0..4095 (pairs)
    const int b  = gg >> 7;            // 128 pairs per batch row
    const int jp = (gg & 127) * 2;     // even feature index

    const int t0 = dir ? (SEQ - 1) : 0;
    const ptrdiff_t stepP = dir ? -(ptrdiff_t)(HID / 2) : (ptrdiff_t)(HID / 2);

    const uint2* xp = reinterpret_cast<const uint2*>(X)
                      + (((size_t)b * SEQ + t0) * HID + jp) / 2;
    const uint32_t* sp = reinterpret_cast<const uint32_t*>(Sg)
                      + (((size_t)b * SEQ + t0) * HID + jp) / 2;

    const size_t ybase = (size_t)b * SEQ * yld + (size_t)t0 * yld + yoff + jp;
    uint2*  ypp = POUT ? reinterpret_cast<uint2*>(Yp + ybase) : nullptr;
    float2* ypf = POUT ? nullptr : reinterpret_cast<float2*>(Yf + ybase);
    const ptrdiff_t ystepP = dir ? -(ptrdiff_t)(yld / 2) : (ptrdiff_t)(yld / 2);

    uint2    xr[PD];
    uint32_t sr[PD];
    #pragma unroll
    for (int d = 0; d < PD; d++) {
        xr[d] = xp[(ptrdiff_t)d * stepP];
        sr[d] = sp[(ptrdiff_t)d * stepP];
    }
    const uint2*    xq = xp + (ptrdiff_t)PD * stepP;
    const uint32_t* sq = sp + (ptrdiff_t)PD * stepP;

    float h0 = 0.f, h1 = 0.f;

    // main loop: SEQ/PD - 1 blocks with prefetch, then 1 epilogue block
    #pragma unroll 1
    for (int blk = 0; blk < SEQ / PD - 1; blk++) {
        #pragma unroll
        for (int d = 0; d < PD; d++) {
            float xv0 = unpack_hl(xr[d].x);
            float xv1 = unpack_hl(xr[d].y);
            __half2 sh = *reinterpret_cast<__half2*>(&sr[d]);
            float2 sf = __half22float2(sh);
            float a0 = 0.5f + sf.x;
            float a1 = 0.5f + sf.y;
            float c0 = fmaf(-a0, xv0, xv0);
            float c1 = fmaf(-a1, xv1, xv1);
            float t0v = fmaf(a0, h0, c0);
            float t1v = fmaf(a1, h1, c1);
            h0 = tanh_fast(xv0 * t0v);
            h1 = tanh_fast(xv1 * t1v);
            if (POUT) {
                uint2 o; o.x = pack_hl(h0); o.y = pack_hl(h1);
                *ypp = o; ypp += ystepP;
            } else {
                float2 o; o.x = h0; o.y = h1;
                *ypf = o; ypf += ystepP;
            }
            xr[d] = *xq;
            sr[d] = *sq;
            xq += stepP;
            sq += stepP;
        }
    }
    // epilogue: last PD steps, no prefetch
    #pragma unroll
    for (int d = 0; d < PD; d++) {
        float xv0 = unpack_hl(xr[d].x);
        float xv1 = unpack_hl(xr[d].y);
        __half2 sh = *reinterpret_cast<__half2*>(&sr[d]);
        float2 sf = __half22float2(sh);
        float a0 = 0.5f + sf.x;
        float a1 = 0.5f + sf.y;
        float c0 = fmaf(-a0, xv0, xv0);
        float c1 = fmaf(-a1, xv1, xv1);
        float t0v = fmaf(a0, h0, c0);
        float t1v = fmaf(a1, h1, c1);
        h0 = tanh_fast(xv0 * t0v);
        h1 = tanh_fast(xv1 * t1v);
        if (POUT) {
            uint2 o; o.x = pack_hl(h0); o.y = pack_hl(h1);
            *ypp = o; ypp += ystepP;
        } else {
            float2 o; o.x = h0; o.y = h1;
            *ypf = o; ypf += ystepP;
        }
    }
}

// ---------------------------------------------------------------------------
__global__ __launch_bounds__(256) void copy_hout(
    const uint32_t* __restrict__ Ypl, const uint32_t* __restrict__ Ypr,
    const float* __restrict__ xx, float* __restrict__ hout)
{
    int gg = blockIdx.x * blockDim.x + threadIdx.x;
    int j = gg & 255;
    int b = (gg >> 8) & 31;
    int s = gg >> 13;
    float v;
    if      (s == 0) v = unpack_hl(Ypl[((size_t)b * SEQ + (SEQ - 1)) * HID + j]);
    else if (s == 1) v = unpack_hl(Ypr[((size_t)b * SEQ) * HID + j]);
    else if (s == 2) v = xx[((size_t)b * SEQ + (SEQ - 1)) * (2 * HID) + j];
    else             v = xx[((size_t)b * SEQ) * (2 * HID) + HID + j];
    hout[gg] = v;
}

// ---------------------------------------------------------------------------
extern "C" void kernel_launch(void* const* d_in, const int* in_sizes, int n_in,
                              void* d_out, int out_size)
{
    const float* x    = (const float*)d_in[0];
    const float* W_fc = (const float*)d_in[1];
    const float* b_fc = (const float*)d_in[2];
    // d_in[3] = W1, d_in[4] = b1 : dead (g1*x + (1-g1)*x == x)
    const float* W2   = (const float*)d_in[5];
    const float* b2   = (const float*)d_in[6];
    float* out = (float*)d_out;

    uint32_t *Pp, *Yp, *W2p;
    __half *S0, *S1;
    cudaGetSymbolAddress((void**)&Pp,  g_Pp);
    cudaGetSymbolAddress((void**)&Yp,  g_Yp);
    cudaGetSymbolAddress((void**)&S0,  g_S0);
    cudaGetSymbolAddress((void**)&S1,  g_S1);
    cudaGetSymbolAddress((void**)&W2p, g_W2p);

    uint32_t* Ypl = Yp;
    uint32_t* Ypr = Yp + (size_t)MROWS * HID;
    float* hout = out + (size_t)BSZ * SEQ * 2 * HID;

    // 0) pre-split W2 (both layers) into packed format
    prep_w<<<2 * HID * HID / 256, 256>>>(W2, W2p);

    // 1) fc projection -> packed P
    {
        dim3 grid(MROWS / 128, 2);
        gemm_fc<<<grid, 256>>>(x, W_fc, b_fc, Pp);
    }

    // 2) layer 0 gates (shared by both dirs) -> (sigma-0.5) fp16
    {
        dim3 grid(MROWS / 128, 2);
        gemm_gate<<<grid, 256>>>(Pp, W2p, b2, S0);
    }

    // 3) layer 0 recurrence -> packed Y  (4096 pairs/dir, 64 blocks x 64 thr)
    {
        dim3 grid(64, 2);
        recur2<true><<<grid, 64>>>(Pp, S0, Ypl, nullptr, HID, 0,
                                   Pp, S0, Ypr, nullptr, HID, 0);
    }

    // 4) layer 1 gates: one GEMM over [2*MROWS, 256]
    {
        dim3 grid(2 * MROWS / 128, 2);
        gemm_gate<<<grid, 256>>>(Yp, W2p + HID * HID, b2 + HID, S1);
    }

    // 5) layer 1 recurrence -> d_out fp32 (feature stride 512)
    {
        dim3 grid(64, 2);
        recur2<false><<<grid, 64>>>(Ypl, S1, nullptr, out, 2 * HID, 0,
                                    Ypr, S1 + (size_t)MROWS * HID, nullptr, out, 2 * HID, HID);
    }

    // 6) final hidden states
    copy_hout<<<BSZ * HID * 4 / 256, 256>>>(Ypl, Ypr, out, hout);
}